// round 16
// baseline (speedup 1.0000x reference)
#include <cuda_runtime.h>
#include <cuda_bf16.h>
#include <cstdint>

// LSTMBaseline: 2-layer LSTM (B=2048, T=512, H=128, in=2) + MLP head -> [B,2]
// Round 16: batch amortization. M=32 rows/CTA (two mma M=16 tiles), 64 CTAs.
// Per-CTA weight traffic (the binding cost) is amortized over 2x rows.
// Layers run SEQUENTIALLY (layer1 gemm -> cell1 -> layer0 gemm -> cell0) so
// only one layer's 32 accumulators are live (register cap). L1C=3 resident
// layer-1 chunks (smem 217KB); x in a separate xs[] array. All components
// (fragment layout, mma4, cell, prefetch, 1 barrier/step) carried from R11.

#define T_STEPS 512
#define HID     128
#define MROWS   32
#define NCTA    64
#define NTHR    512
#define HSTR    68            // h-row stride in bf16-pairs; HSTR/4 odd -> LDSM conflict-free
#define PB      (MROWS * HSTR * 4)   // phase stride in bytes (8704)
#define TB      (16 * HSTR * 4)      // tile-B offset in bytes (4352)

#define L0KP    8             // layer0 k-chunks (128 h; x via FFMA path)
#define L1KP    16            // layer1 k-chunks (128 h0 | 128 h1)
#define L1C     3             // layer1 k-chunks cached in smem
#define NSTREAM (L1KP - L1C)  // 13 streamed k-chunks

// uint4 = {gtA.b0, gtA.b1, gtB.b0, gtB.b1}, gtA=2p, gtB=2p+1
// index: ((w*KP + kp)*2 + p)*32 + lane
__device__ uint4 d_WB0u[16 * L0KP * 2 * 32];   // 131072 B
__device__ uint4 d_WB1u[16 * L1KP * 2 * 32];   // 262144 B
__device__ uint4 d_XW0[128];                   // x-weights: (w*4+c0)*2+q, bf16 pairs
__device__ float d_B0[512];
__device__ float d_B1[512];

__device__ __forceinline__ uint32_t pack_bf2(float a, float b)
{
    __nv_bfloat162 p = __floats2bfloat162_rn(a, b);
    return *reinterpret_cast<uint32_t*>(&p);
}

__global__ void prep_kernel(const float* __restrict__ w_hh0, const float* __restrict__ w_ih0,
                            const float* __restrict__ b_ih0, const float* __restrict__ b_hh0,
                            const float* __restrict__ w_ih1, const float* __restrict__ w_hh1,
                            const float* __restrict__ b_ih1, const float* __restrict__ b_hh1)
{
    int idx = blockIdx.x * blockDim.x + threadIdx.x;
    int l = idx & 31, c = l & 3;
    int r = idx >> 5;

    if (idx < 16 * L0KP * 2 * 32) {           // ---- WB0 (pure w_hh0, K=128) ----
        int p = r & 1, rr = r >> 1;
        int kp = rr % L0KP, w = rr / L0KP;
        int n = w * 8 + (l >> 2);
        float v[2][4];
#pragma unroll
        for (int j = 0; j < 2; j++) {
            int g = (2 * p + j) * 128 + n;
#pragma unroll
            for (int q = 0; q < 4; q++) {
                int k = kp * 16 + (q >> 1) * 8 + c * 2 + (q & 1);
                v[j][q] = w_hh0[g * 128 + k];
            }
        }
        d_WB0u[idx] = make_uint4(
            pack_bf2(v[0][0], v[0][1]), pack_bf2(v[0][2], v[0][3]),
            pack_bf2(v[1][0], v[1][1]), pack_bf2(v[1][2], v[1][3]));
    }
    if (idx < 16 * L1KP * 2 * 32) {           // ---- WB1 (K=256: h0|h1) ----
        int p = r & 1, rr = r >> 1;
        int kp = rr % L1KP, w = rr / L1KP;
        int n = w * 8 + (l >> 2);
        const float* src = (kp < 8) ? w_ih1 : w_hh1;
        float v[2][4];
#pragma unroll
        for (int j = 0; j < 2; j++) {
            int g = (2 * p + j) * 128 + n;
#pragma unroll
            for (int q = 0; q < 4; q++) {
                int kk = (kp & 7) * 16 + (q >> 1) * 8 + c * 2 + (q & 1);
                v[j][q] = src[g * 128 + kk];
            }
        }
        d_WB1u[idx] = make_uint4(
            pack_bf2(v[0][0], v[0][1]), pack_bf2(v[0][2], v[0][3]),
            pack_bf2(v[1][0], v[1][1]), pack_bf2(v[1][2], v[1][3]));
    }
    if (idx < 64) {                           // ---- XW0 ----
        int w = idx >> 2, c0 = idx & 3;
        uint32_t pr[8];
#pragma unroll
        for (int gt = 0; gt < 4; gt++)
#pragma unroll
            for (int j = 0; j < 2; j++) {
                int g = gt * 128 + w * 8 + 2 * c0 + j;
                pr[gt * 2 + j] = pack_bf2(w_ih0[g * 2 + 0], w_ih0[g * 2 + 1]);
            }
        d_XW0[idx * 2 + 0] = make_uint4(pr[0], pr[1], pr[2], pr[3]);
        d_XW0[idx * 2 + 1] = make_uint4(pr[4], pr[5], pr[6], pr[7]);
    }
    if (idx < 512) {
        d_B0[idx] = b_ih0[idx] + b_hh0[idx];
        d_B1[idx] = b_ih1[idx] + b_hh1[idx];
    }
}

__device__ __forceinline__ void mma16(float acc[4], uint32_t a0, uint32_t a1,
                                      uint32_t a2, uint32_t a3, uint32_t b0, uint32_t b1)
{
    asm volatile(
        "mma.sync.aligned.m16n8k16.row.col.f32.bf16.bf16.f32 "
        "{%0,%1,%2,%3}, {%4,%5,%6,%7}, {%8,%9}, {%0,%1,%2,%3};\n"
        : "+f"(acc[0]), "+f"(acc[1]), "+f"(acc[2]), "+f"(acc[3])
        : "r"(a0), "r"(a1), "r"(a2), "r"(a3), "r"(b0), "r"(b1));
}

#define LDSM4(a0, a1, a2, a3, addr)                                       \
    asm volatile("ldmatrix.sync.aligned.m8n8.x4.shared.b16 "              \
                 "{%0,%1,%2,%3}, [%4];"                                   \
                 : "=r"(a0), "=r"(a1), "=r"(a2), "=r"(a3) : "r"(addr))

__device__ __forceinline__ float tanha(float x)
{
    float y;
    asm("tanh.approx.f32 %0, %1;" : "=f"(y) : "f"(x));
    return y;
}
__device__ __forceinline__ float sigf(float x)
{
    return fmaf(tanha(0.5f * x), 0.5f, 0.5f);
}

__device__ __forceinline__ void mma4(float acc[4][4], uint32_t a0, uint32_t a1,
                                     uint32_t a2, uint32_t a3, uint4 w01, uint4 w23)
{
    mma16(acc[0], a0, a1, a2, a3, w01.x, w01.y);
    mma16(acc[1], a0, a1, a2, a3, w01.z, w01.w);
    mma16(acc[2], a0, a1, a2, a3, w23.x, w23.y);
    mma16(acc[3], a0, a1, a2, a3, w23.z, w23.w);
}

// dual-tile: same weights applied to tile-A and tile-B A-fragments
__device__ __forceinline__ void mma4x2(float accA[4][4], float accB[4][4],
                                       uint32_t baddr, uint4 w01, uint4 w23)
{
    uint32_t a0, a1, a2, a3;
    LDSM4(a0, a1, a2, a3, baddr);
    mma4(accA, a0, a1, a2, a3, w01, w23);
    LDSM4(a0, a1, a2, a3, baddr + TB);
    mma4(accB, a0, a1, a2, a3, w01, w23);
}

__device__ __forceinline__ void acc_init(float acc[4][4], const float* bs)
{
#pragma unroll
    for (int gt = 0; gt < 4; gt++) {
        acc[gt][0] = bs[gt * 2];  acc[gt][1] = bs[gt * 2 + 1];
        acc[gt][2] = bs[gt * 2];  acc[gt][3] = bs[gt * 2 + 1];
    }
}

__device__ __forceinline__ float2 unp_bf2(uint32_t u)
{
    return __bfloat1622float2(*reinterpret_cast<const __nv_bfloat162*>(&u));
}

// x-projection: acc += x(row) . w_ih0; x from xs slots (bf16 pairs)
__device__ __forceinline__ void xproj(float acc[4][4], uint32_t xsa, uint32_t xsb,
                                      const uint4* __restrict__ sxw, int c0, int w)
{
    float2 x0 = unp_bf2(xsa);
    float2 x1 = unp_bf2(xsb);
    uint4 xa = sxw[(w * 4 + c0) * 2 + 0];
    uint4 xb = sxw[(w * 4 + c0) * 2 + 1];
    uint32_t pr[8] = {xa.x, xa.y, xa.z, xa.w, xb.x, xb.y, xb.z, xb.w};
#pragma unroll
    for (int gt = 0; gt < 4; gt++)
#pragma unroll
        for (int j = 0; j < 2; j++) {
            float2 wv = unp_bf2(pr[gt * 2 + j]);
            acc[gt][0 + j] = fmaf(x0.x, wv.x, fmaf(x0.y, wv.y, acc[gt][0 + j]));
            acc[gt][2 + j] = fmaf(x1.x, wv.x, fmaf(x1.y, wv.y, acc[gt][2 + j]));
        }
}

__device__ __forceinline__ void cell(const float acc[4][4], float* cs,
                                     uint32_t* __restrict__ hdst, int r0, int c0, int w)
{
#pragma unroll
    for (int rg = 0; rg < 2; rg++) {
        float hv[2];
#pragma unroll
        for (int j = 0; j < 2; j++) {
            int idx = rg * 2 + j;
            float i_ = sigf(acc[0][idx]);
            float f_ = sigf(acc[1][idx]);
            float g_ = tanha(acc[2][idx]);
            float o_ = sigf(acc[3][idx]);
            float cv = fmaf(f_, cs[idx], i_ * g_);
            cs[idx] = cv;
            hv[j] = o_ * tanha(cv);
        }
        hdst[(r0 + 8 * rg) * HSTR + w * 4 + c0] = pack_bf2(hv[0], hv[1]);
    }
}

#define SW0_U4 (16 * L0KP * 2 * 32)           // 8192 uint4  = 131072 B
#define SW1_U4 (16 * L1C * 2 * 32)            // 3072 uint4  = 49152 B
#define HBUF   (2 * MROWS * HSTR)             // 4352 uint32 per layer pair
#define OFF_SXW (SW0_U4 * 16 + SW1_U4 * 16)
#define OFF_H0  (OFF_SXW + 2048)
#define OFF_H1  (OFF_H0 + HBUF * 4)
#define OFF_XS  (OFF_H1 + HBUF * 4)
#define SMEM_SZ (OFF_XS + 256)                // 217600 B

__global__ void __launch_bounds__(NTHR, 1)
lstm_main(const float* __restrict__ hr, const float* __restrict__ glu,
          const float* __restrict__ w1, const float* __restrict__ b1,
          const float* __restrict__ w2, const float* __restrict__ b2,
          float* __restrict__ out)
{
    extern __shared__ char smem_raw[];
    uint4*    sw0 = reinterpret_cast<uint4*>(smem_raw);
    uint4*    sw1 = reinterpret_cast<uint4*>(smem_raw + SW0_U4 * 16);
    uint4*    sxw = reinterpret_cast<uint4*>(smem_raw + OFF_SXW);
    uint32_t* h0e = reinterpret_cast<uint32_t*>(smem_raw + OFF_H0);
    uint32_t* h1e = reinterpret_cast<uint32_t*>(smem_raw + OFF_H1);
    uint32_t* xs  = reinterpret_cast<uint32_t*>(smem_raw + OFF_XS);
    float*    hid_s = reinterpret_cast<float*>(smem_raw);   // overlay after loop

    const int tid = threadIdx.x;
    const int l = tid & 31, w = tid >> 5;
    const int r0 = l >> 2, c0 = l & 3;
    const int B0 = blockIdx.x * MROWS;

    // ---- load resident weights ----
    for (int i = tid; i < SW0_U4; i += NTHR) sw0[i] = d_WB0u[i];
    for (int i = tid; i < SW1_U4; i += NTHR) {
        int ll = i & 31, r = i >> 5;
        int p = r & 1, rr = r >> 1;
        int kp = rr % L1C, ww = rr / L1C;
        sw1[i] = d_WB1u[((ww * L1KP + kp) * 2 + p) * 32 + ll];
    }
    if (tid < 128) sxw[tid] = d_XW0[tid];
    for (int i = tid; i < HBUF; i += NTHR) { h0e[i] = 0u; h1e[i] = 0u; }
    if (tid < 64) xs[tid] = 0u;
    __syncthreads();
    if (tid < MROWS)    // x_0 -> xs phase 0
        xs[tid] = pack_bf2(hr[(B0 + tid) * T_STEPS], glu[(B0 + tid) * T_STEPS]);

    float bs0[8], bs1[8];
#pragma unroll
    for (int gt = 0; gt < 4; gt++)
#pragma unroll
        for (int j = 0; j < 2; j++) {
            int g = gt * 128 + w * 8 + 2 * c0 + j;
            bs0[gt * 2 + j] = d_B0[g];
            bs1[gt * 2 + j] = d_B1[g];
        }

    float cs0a[4] = {0, 0, 0, 0}, cs0b[4] = {0, 0, 0, 0};
    float cs1a[4] = {0, 0, 0, 0}, cs1b[4] = {0, 0, 0, 0};

    // per-thread ldmatrix address offset (within a 16-row tile)
    const uint32_t aoff = (uint32_t)((l & 15) * (HSTR * 4) + ((l >> 4) << 4));
    const uint32_t h0u = (uint32_t)__cvta_generic_to_shared(h0e) + aoff;
    const uint32_t h1u = (uint32_t)__cvta_generic_to_shared(h1e) + aoff;

    const uint4* ws0 = sw0 + (w * L0KP) * 64 + l;             // [kp*64 + p*32]
    const uint4* ws1 = sw1 + (w * L1C) * 64 + l;
    const uint4* wg1 = d_WB1u + ((w * L1KP + L1C) * 2) * 32 + l;   // streamed s: [s*64 + p*32]

    __syncthreads();

    // ---- prologue: h0_0 = cell0(0, x_0) for both tiles -> phase 1 ----
    {
        float accA[4][4], accB[4][4];
        acc_init(accA, bs0);
        acc_init(accB, bs0);
        xproj(accA, xs[r0], xs[r0 + 8], sxw, c0, w);
        xproj(accB, xs[16 + r0], xs[16 + r0 + 8], sxw, c0, w);
        cell(accA, cs0a, h0e + MROWS * HSTR, r0, c0, w);
        cell(accB, cs0b, h0e + MROWS * HSTR + 16 * HSTR, r0, c0, w);
        if (tid < MROWS)   // x_1 -> xs phase 1
            xs[32 + tid] = pack_bf2(hr[(B0 + tid) * T_STEPS + 1],
                                    glu[(B0 + tid) * T_STEPS + 1]);
        __syncthreads();
    }

    int cur = 1;
#pragma unroll 1
    for (int t = 0; t < T_STEPS; t++) {
        const int nxt = cur ^ 1;
        const uint32_t h0b = h0u + cur * PB;      // h0_t
        const uint32_t h1b = h1u + cur * PB;      // h1_{t-1}
        float accA[4][4], accB[4][4];

        // ======== layer 1: gates = h0_t @ Wih1 + h1_{t-1} @ Whh1 + b1 ========
        acc_init(accA, bs1);
        acc_init(accB, bs1);
        uint4 Wc0 = __ldg(wg1), Wc1 = __ldg(wg1 + 32);

#pragma unroll
        for (int kp = 0; kp < 8; kp++) {          // h0 chunks
            if (kp < L1C) {
                mma4x2(accA, accB, h0b + kp * 32, ws1[kp * 64], ws1[kp * 64 + 32]);
            } else {
                uint4 w01 = Wc0, w23 = Wc1;
                int s = kp - L1C;                 // 0..4
                Wc0 = __ldg(wg1 + (s + 1) * 64);
                Wc1 = __ldg(wg1 + (s + 1) * 64 + 32);
                mma4x2(accA, accB, h0b + kp * 32, w01, w23);
            }
        }
#pragma unroll
        for (int kp = 0; kp < 8; kp++) {          // h1 chunks (streamed s = 5..12)
            uint4 w01 = Wc0, w23 = Wc1;
            int s = 5 + kp;
            if (s + 1 < NSTREAM) {
                Wc0 = __ldg(wg1 + (s + 1) * 64);
                Wc1 = __ldg(wg1 + (s + 1) * 64 + 32);
            }
            mma4x2(accA, accB, h1b + kp * 32, w01, w23);
        }

        // ---- cell1 (MUFU overlaps the layer-0 gemm below) ----
        cell(accA, cs1a, h1e + nxt * MROWS * HSTR, r0, c0, w);
        cell(accB, cs1b, h1e + nxt * MROWS * HSTR + 16 * HSTR, r0, c0, w);

        // x_{t+2} prefetch: LDG here, STS after cell0 (R5/R11 pattern)
        float xr_n = 0.f, xg_n = 0.f;
        if (tid < MROWS && t + 2 < T_STEPS) {
            xr_n = hr[(B0 + tid) * T_STEPS + t + 2];
            xg_n = glu[(B0 + tid) * T_STEPS + t + 2];
        }

        // ======== layer 0: gates = h0_t @ Whh0 + x_{t+1} . Wih0 + b0 ========
        acc_init(accA, bs0);
        acc_init(accB, bs0);
#pragma unroll
        for (int kp = 0; kp < L0KP; kp++)
            mma4x2(accA, accB, h0b + kp * 32, ws0[kp * 64], ws0[kp * 64 + 32]);

        xproj(accA, xs[cur * 32 + r0], xs[cur * 32 + r0 + 8], sxw, c0, w);
        xproj(accB, xs[cur * 32 + 16 + r0], xs[cur * 32 + 16 + r0 + 8], sxw, c0, w);
        cell(accA, cs0a, h0e + nxt * MROWS * HSTR, r0, c0, w);
        cell(accB, cs0b, h0e + nxt * MROWS * HSTR + 16 * HSTR, r0, c0, w);

        if (tid < MROWS)
            xs[nxt * 32 + tid] = pack_bf2(xr_n, xg_n);

        __syncthreads();
        cur = nxt;
    }
    // final h1_511 in h1e phase cur; smem weights now dead.

    // ---- head: hidden = relu(h1 @ w1^T + b1), 32 rows ----
    {
        int ff = tid & 63;
        int mq = tid >> 6;                        // 0..7
        const float2* w1p = reinterpret_cast<const float2*>(w1 + ff * HID);
#pragma unroll
        for (int j = 0; j < 4; j++) {
            int m = mq + j * 8;
            float s = b1[ff];
            const uint32_t* hp = h1e + cur * MROWS * HSTR + m * HSTR;
#pragma unroll 8
            for (int p = 0; p < 64; p++) {
                float2 hv = unp_bf2(hp[p]);
                float2 wv = w1p[p];
                s = fmaf(hv.x, wv.x, s);
                s = fmaf(hv.y, wv.y, s);
            }
            hid_s[m * 64 + ff] = fmaxf(s, 0.f);
        }
    }
    __syncthreads();

    // ---- head: out = hidden @ w2^T + b2 ----
    if (tid < 64) {
        int m = tid >> 1, o = tid & 1;
        float s = b2[o];
#pragma unroll 8
        for (int k = 0; k < 64; k++)
            s = fmaf(hid_s[m * 64 + k], w2[o * 64 + k], s);
        out[(B0 + m) * 2 + o] = s;
    }
}

extern "C" void kernel_launch(void* const* d_in, const int* in_sizes, int n_in,
                              void* d_out, int out_size)
{
    const float* hr   = (const float*)d_in[0];
    const float* glu  = (const float*)d_in[1];
    const float* wih0 = (const float*)d_in[2];
    const float* whh0 = (const float*)d_in[3];
    const float* bih0 = (const float*)d_in[4];
    const float* bhh0 = (const float*)d_in[5];
    const float* wih1 = (const float*)d_in[6];
    const float* whh1 = (const float*)d_in[7];
    const float* bih1 = (const float*)d_in[8];
    const float* bhh1 = (const float*)d_in[9];
    const float* w1   = (const float*)d_in[10];
    const float* b1   = (const float*)d_in[11];
    const float* w2   = (const float*)d_in[12];
    const float* b2   = (const float*)d_in[13];
    float* out = (float*)d_out;

    cudaFuncSetAttribute(lstm_main, cudaFuncAttributeMaxDynamicSharedMemorySize, SMEM_SZ);

    prep_kernel<<<128, 256>>>(whh0, wih0, bih0, bhh0, wih1, whh1, bih1, bhh1);
    lstm_main<<<NCTA, NTHR, SMEM_SZ>>>(hr, glu, w1, b1, w2, b2, out);
}

// round 17
// speedup vs baseline: 1.8504x; 1.8504x over previous
#include <cuda_runtime.h>
#include <cuda_bf16.h>
#include <cstdint>

// LSTMBaseline: 2-layer LSTM (B=2048, T=512, H=128, in=2) + MLP head -> [B,2]
// Round 17: warp fusion of R11. 128 CTAs x 256 thr (8 warps), M=16 rows/CTA.
// Each warp = two fused R11 warps (16 gate-cols): A-fragments (ldmatrix)
// loaded ONCE per chunk and shared by both halves -> total A-LDSM traffic
// halves (-12.5% L1 port). Weight packing/layouts/math identical to R11;
// register cap at 256 thr is 255 so the doubled accumulators fit freely.

#define T_STEPS 512
#define HID     128
#define MROWS   16
#define NCTA    128
#define NTHR    256
#define HSTR    68            // h-row stride in bf16-pairs; conflict-free
#define PB      (MROWS * HSTR * 4)   // phase stride in bytes

#define L0KP    8             // layer0 k-chunks (128 h; x via FFMA path)
#define L1KP    16            // layer1 k-chunks (128 h0 | 128 h1)
#define L1C     5             // layer1 k-chunks cached in smem
#define NSTREAM (L1KP - L1C)  // 11 streamed k-chunks

// uint4 = {gtA.b0, gtA.b1, gtB.b0, gtB.b1}, gtA=2p, gtB=2p+1
// index: ((ow*KP + kp)*2 + p)*32 + lane   (ow = R11 warp id 0..15)
__device__ uint4 d_WB0u[16 * L0KP * 2 * 32];   // 131072 B
__device__ uint4 d_WB1u[16 * L1KP * 2 * 32];   // 262144 B
__device__ uint4 d_XW0[128];                   // x-weights: (ow*4+c0)*2+q, bf16 pairs
__device__ float d_B0[512];
__device__ float d_B1[512];

__device__ __forceinline__ uint32_t pack_bf2(float a, float b)
{
    __nv_bfloat162 p = __floats2bfloat162_rn(a, b);
    return *reinterpret_cast<uint32_t*>(&p);
}

__global__ void prep_kernel(const float* __restrict__ w_hh0, const float* __restrict__ w_ih0,
                            const float* __restrict__ b_ih0, const float* __restrict__ b_hh0,
                            const float* __restrict__ w_ih1, const float* __restrict__ w_hh1,
                            const float* __restrict__ b_ih1, const float* __restrict__ b_hh1)
{
    int idx = blockIdx.x * blockDim.x + threadIdx.x;
    int l = idx & 31, c = l & 3;
    int r = idx >> 5;

    if (idx < 16 * L0KP * 2 * 32) {           // ---- WB0 (pure w_hh0, K=128) ----
        int p = r & 1, rr = r >> 1;
        int kp = rr % L0KP, w = rr / L0KP;
        int n = w * 8 + (l >> 2);
        float v[2][4];
#pragma unroll
        for (int j = 0; j < 2; j++) {
            int g = (2 * p + j) * 128 + n;
#pragma unroll
            for (int q = 0; q < 4; q++) {
                int k = kp * 16 + (q >> 1) * 8 + c * 2 + (q & 1);
                v[j][q] = w_hh0[g * 128 + k];
            }
        }
        d_WB0u[idx] = make_uint4(
            pack_bf2(v[0][0], v[0][1]), pack_bf2(v[0][2], v[0][3]),
            pack_bf2(v[1][0], v[1][1]), pack_bf2(v[1][2], v[1][3]));
    }
    if (idx < 16 * L1KP * 2 * 32) {           // ---- WB1 (K=256: h0|h1) ----
        int p = r & 1, rr = r >> 1;
        int kp = rr % L1KP, w = rr / L1KP;
        int n = w * 8 + (l >> 2);
        const float* src = (kp < 8) ? w_ih1 : w_hh1;
        float v[2][4];
#pragma unroll
        for (int j = 0; j < 2; j++) {
            int g = (2 * p + j) * 128 + n;
#pragma unroll
            for (int q = 0; q < 4; q++) {
                int kk = (kp & 7) * 16 + (q >> 1) * 8 + c * 2 + (q & 1);
                v[j][q] = src[g * 128 + kk];
            }
        }
        d_WB1u[idx] = make_uint4(
            pack_bf2(v[0][0], v[0][1]), pack_bf2(v[0][2], v[0][3]),
            pack_bf2(v[1][0], v[1][1]), pack_bf2(v[1][2], v[1][3]));
    }
    if (idx < 64) {                           // ---- XW0: w_ih0 bf16-pair table ----
        int w = idx >> 2, c0 = idx & 3;
        uint32_t pr[8];
#pragma unroll
        for (int gt = 0; gt < 4; gt++)
#pragma unroll
            for (int j = 0; j < 2; j++) {
                int g = gt * 128 + w * 8 + 2 * c0 + j;
                pr[gt * 2 + j] = pack_bf2(w_ih0[g * 2 + 0], w_ih0[g * 2 + 1]);
            }
        d_XW0[idx * 2 + 0] = make_uint4(pr[0], pr[1], pr[2], pr[3]);
        d_XW0[idx * 2 + 1] = make_uint4(pr[4], pr[5], pr[6], pr[7]);
    }
    if (idx < 512) {
        d_B0[idx] = b_ih0[idx] + b_hh0[idx];
        d_B1[idx] = b_ih1[idx] + b_hh1[idx];
    }
}

__device__ __forceinline__ void mma16(float acc[4], uint32_t a0, uint32_t a1,
                                      uint32_t a2, uint32_t a3, uint32_t b0, uint32_t b1)
{
    asm volatile(
        "mma.sync.aligned.m16n8k16.row.col.f32.bf16.bf16.f32 "
        "{%0,%1,%2,%3}, {%4,%5,%6,%7}, {%8,%9}, {%0,%1,%2,%3};\n"
        : "+f"(acc[0]), "+f"(acc[1]), "+f"(acc[2]), "+f"(acc[3])
        : "r"(a0), "r"(a1), "r"(a2), "r"(a3), "r"(b0), "r"(b1));
}

#define LDSM4(a0, a1, a2, a3, addr)                                       \
    asm volatile("ldmatrix.sync.aligned.m8n8.x4.shared.b16 "              \
                 "{%0,%1,%2,%3}, [%4];"                                   \
                 : "=r"(a0), "=r"(a1), "=r"(a2), "=r"(a3) : "r"(addr))

__device__ __forceinline__ float tanha(float x)
{
    float y;
    asm("tanh.approx.f32 %0, %1;" : "=f"(y) : "f"(x));
    return y;
}
__device__ __forceinline__ float sigf(float x)
{
    return fmaf(tanha(0.5f * x), 0.5f, 0.5f);
}

__device__ __forceinline__ void mma4(float acc[4][4], uint32_t a0, uint32_t a1,
                                     uint32_t a2, uint32_t a3, uint4 w01, uint4 w23)
{
    mma16(acc[0], a0, a1, a2, a3, w01.x, w01.y);
    mma16(acc[1], a0, a1, a2, a3, w01.z, w01.w);
    mma16(acc[2], a0, a1, a2, a3, w23.x, w23.y);
    mma16(acc[3], a0, a1, a2, a3, w23.z, w23.w);
}

__device__ __forceinline__ void acc_init(float acc[4][4], const float* bs)
{
#pragma unroll
    for (int gt = 0; gt < 4; gt++) {
        acc[gt][0] = bs[gt * 2];  acc[gt][1] = bs[gt * 2 + 1];
        acc[gt][2] = bs[gt * 2];  acc[gt][3] = bs[gt * 2 + 1];
    }
}

__device__ __forceinline__ float2 unp_bf2(uint32_t u)
{
    return __bfloat1622float2(*reinterpret_cast<const __nv_bfloat162*>(&u));
}

// x-projection for old-warp ow: acc += x(row) . w_ih0
__device__ __forceinline__ void xproj(float acc[4][4],
                                      const uint32_t* __restrict__ h0cur32,
                                      const uint4* __restrict__ sxw,
                                      int r0, int c0, int ow)
{
    float2 x0 = unp_bf2(h0cur32[r0 * HSTR + 64]);
    float2 x1 = unp_bf2(h0cur32[(r0 + 8) * HSTR + 64]);
    uint4 xa = sxw[(ow * 4 + c0) * 2 + 0];
    uint4 xb = sxw[(ow * 4 + c0) * 2 + 1];
    uint32_t pr[8] = {xa.x, xa.y, xa.z, xa.w, xb.x, xb.y, xb.z, xb.w};
#pragma unroll
    for (int gt = 0; gt < 4; gt++)
#pragma unroll
        for (int j = 0; j < 2; j++) {
            float2 wv = unp_bf2(pr[gt * 2 + j]);
            acc[gt][0 + j] = fmaf(x0.x, wv.x, fmaf(x0.y, wv.y, acc[gt][0 + j]));
            acc[gt][2 + j] = fmaf(x1.x, wv.x, fmaf(x1.y, wv.y, acc[gt][2 + j]));
        }
}

__device__ __forceinline__ void cell(const float acc[4][4], float* cs,
                                     uint32_t* __restrict__ hdst, int r0, int c0, int ow)
{
#pragma unroll
    for (int rg = 0; rg < 2; rg++) {
        float hv[2];
#pragma unroll
        for (int j = 0; j < 2; j++) {
            int idx = rg * 2 + j;
            float i_ = sigf(acc[0][idx]);
            float f_ = sigf(acc[1][idx]);
            float g_ = tanha(acc[2][idx]);
            float o_ = sigf(acc[3][idx]);
            float cv = fmaf(f_, cs[idx], i_ * g_);
            cs[idx] = cv;
            hv[j] = o_ * tanha(cv);
        }
        hdst[(r0 + 8 * rg) * HSTR + ow * 4 + c0] = pack_bf2(hv[0], hv[1]);
    }
}

#define SW0_U4 (16 * L0KP * 2 * 32)           // 8192 uint4  = 131072 B
#define SW1_U4 (16 * L1C * 2 * 32)            // 5120 uint4  = 81920 B
#define HBUF   (2 * MROWS * HSTR)             // 2176 uint32 per layer pair
#define SMEM_SZ (SW0_U4 * 16 + SW1_U4 * 16 + 2048 + 2 * HBUF * 4)  // 232448 B

// per-old-warp strides (uint4 units)
#define W0STR  (L0KP * 2 * 32)
#define W1RSTR (L1C * 2 * 32)
#define W1GSTR (L1KP * 2 * 32)

__global__ void __launch_bounds__(NTHR, 1)
lstm_main(const float* __restrict__ hr, const float* __restrict__ glu,
          const float* __restrict__ w1, const float* __restrict__ b1,
          const float* __restrict__ w2, const float* __restrict__ b2,
          float* __restrict__ out)
{
    extern __shared__ char smem_raw[];
    uint4*    sw0 = reinterpret_cast<uint4*>(smem_raw);
    uint4*    sw1 = reinterpret_cast<uint4*>(smem_raw + SW0_U4 * 16);
    uint4*    sxw = reinterpret_cast<uint4*>(smem_raw + SW0_U4 * 16 + SW1_U4 * 16);
    uint32_t* h0e = reinterpret_cast<uint32_t*>(smem_raw + SW0_U4 * 16 + SW1_U4 * 16 + 2048);
    uint32_t* h1e = h0e + HBUF;
    float*    hid_s = reinterpret_cast<float*>(smem_raw);   // overlay after loop

    const int tid = threadIdx.x;
    const int l = tid & 31, w = tid >> 5;     // w = fused warp 0..7
    const int r0 = l >> 2, c0 = l & 3;
    const int B0 = blockIdx.x * MROWS;

    // ---- load resident weights ----
    for (int i = tid; i < SW0_U4; i += NTHR) sw0[i] = d_WB0u[i];
    for (int i = tid; i < SW1_U4; i += NTHR) {
        int ll = i & 31, r = i >> 5;
        int p = r & 1, rr = r >> 1;
        int kp = rr % L1C, ww = rr / L1C;
        sw1[i] = d_WB1u[((ww * L1KP + kp) * 2 + p) * 32 + ll];
    }
    if (tid < 128) sxw[tid] = d_XW0[tid];
    for (int i = tid; i < HBUF; i += NTHR) { h0e[i] = 0u; h1e[i] = 0u; }
    __syncthreads();
    if (tid < MROWS)    // x_0 -> pair 64 of h0e phase 0
        h0e[tid * HSTR + 64] = pack_bf2(hr[(B0 + tid) * T_STEPS], glu[(B0 + tid) * T_STEPS]);

    // per-half biases (old warps 2w, 2w+1)
    float bs0[2][8], bs1[2][8];
#pragma unroll
    for (int hh = 0; hh < 2; hh++) {
        int ow = 2 * w + hh;
#pragma unroll
        for (int gt = 0; gt < 4; gt++)
#pragma unroll
            for (int j = 0; j < 2; j++) {
                int g = gt * 128 + ow * 8 + 2 * c0 + j;
                bs0[hh][gt * 2 + j] = d_B0[g];
                bs1[hh][gt * 2 + j] = d_B1[g];
            }
    }

    float cs0[2][4] = {{0, 0, 0, 0}, {0, 0, 0, 0}};
    float cs1[2][4] = {{0, 0, 0, 0}, {0, 0, 0, 0}};

    // per-thread ldmatrix address offset
    const uint32_t aoff = (uint32_t)((l & 15) * (HSTR * 4) + ((l >> 4) << 4));
    const uint32_t h0u = (uint32_t)__cvta_generic_to_shared(h0e) + aoff;
    const uint32_t h1u = (uint32_t)__cvta_generic_to_shared(h1e) + aoff;

    // per-half weight base pointers
    const uint4* ws0p[2] = { sw0 + (2 * w) * W0STR + l,  sw0 + (2 * w + 1) * W0STR + l };
    const uint4* ws1p[2] = { sw1 + (2 * w) * W1RSTR + l, sw1 + (2 * w + 1) * W1RSTR + l };
    const uint4* wg1p[2] = { d_WB1u + (2 * w) * W1GSTR + L1C * 64 + l,
                             d_WB1u + (2 * w + 1) * W1GSTR + L1C * 64 + l };

    __syncthreads();

    // ---- prologue: h0_0 from [h0=0, x_0] ----
    {
        float acc0[2][4][4];
#pragma unroll
        for (int hh = 0; hh < 2; hh++) acc_init(acc0[hh], bs0[hh]);
#pragma unroll
        for (int kp = 0; kp < L0KP; kp++) {
            uint32_t a0, a1, a2, a3;
            LDSM4(a0, a1, a2, a3, h0u + kp * 32);
#pragma unroll
            for (int hh = 0; hh < 2; hh++)
                mma4(acc0[hh], a0, a1, a2, a3, ws0p[hh][kp * 64], ws0p[hh][kp * 64 + 32]);
        }
#pragma unroll
        for (int hh = 0; hh < 2; hh++) {
            xproj(acc0[hh], h0e, sxw, r0, c0, 2 * w + hh);
            cell(acc0[hh], cs0[hh], h0e + MROWS * HSTR, r0, c0, 2 * w + hh);
        }
        if (tid < MROWS)
            h0e[MROWS * HSTR + tid * HSTR + 64] =
                pack_bf2(hr[(B0 + tid) * T_STEPS + 1], glu[(B0 + tid) * T_STEPS + 1]);
        __syncthreads();
    }

    int cur = 1;
#pragma unroll 1
    for (int t = 0; t < T_STEPS; t++) {
        const int nxt = cur ^ 1;
        const uint32_t* h0cur32 = h0e + cur * MROWS * HSTR;   // h0_t (+ x_{t+1})
        const uint32_t h0b = h0u + cur * PB;
        const uint32_t h1b = h1u + cur * PB;                  // h1_{t-1}
        float acc1[2][4][4], acc0[2][4][4];
#pragma unroll
        for (int hh = 0; hh < 2; hh++) {
            acc_init(acc1[hh], bs1[hh]);
            acc_init(acc0[hh], bs0[hh]);
        }

        uint4 Wc0[2], Wc1[2];
#pragma unroll
        for (int hh = 0; hh < 2; hh++) {
            Wc0[hh] = __ldg(wg1p[hh]);
            Wc1[hh] = __ldg(wg1p[hh] + 32);
        }

        // ---- merged h0 pass: layer1 (all 8 kp) + layer0 (all 8 kp) ----
#pragma unroll
        for (int kp = 0; kp < 8; kp++) {
            uint32_t a0, a1, a2, a3;
            LDSM4(a0, a1, a2, a3, h0b + kp * 32);
            if (kp < L1C) {
#pragma unroll
                for (int hh = 0; hh < 2; hh++)
                    mma4(acc1[hh], a0, a1, a2, a3,
                         ws1p[hh][kp * 64], ws1p[hh][kp * 64 + 32]);
            } else {
                int s = kp - L1C;                       // 0..2
#pragma unroll
                for (int hh = 0; hh < 2; hh++) {
                    uint4 w01 = Wc0[hh], w23 = Wc1[hh];
                    Wc0[hh] = __ldg(wg1p[hh] + (s + 1) * 64);
                    Wc1[hh] = __ldg(wg1p[hh] + (s + 1) * 64 + 32);
                    mma4(acc1[hh], a0, a1, a2, a3, w01, w23);
                }
            }
#pragma unroll
            for (int hh = 0; hh < 2; hh++)
                mma4(acc0[hh], a0, a1, a2, a3,
                     ws0p[hh][kp * 64], ws0p[hh][kp * 64 + 32]);
        }

        // ---- x-projection + cell0 (MUFU overlaps h1 tensor stream) ----
#pragma unroll
        for (int hh = 0; hh < 2; hh++) {
            xproj(acc0[hh], h0cur32, sxw, r0, c0, 2 * w + hh);
            cell(acc0[hh], cs0[hh], h0e + nxt * MROWS * HSTR, r0, c0, 2 * w + hh);
        }
        if (tid < MROWS && t + 2 < T_STEPS)
            h0e[nxt * MROWS * HSTR + tid * HSTR + 64] =
                pack_bf2(hr[(B0 + tid) * T_STEPS + t + 2],
                         glu[(B0 + tid) * T_STEPS + t + 2]);

        // ---- h1 pass: layer1 kp 8..15 (streamed s = 3..10) ----
#pragma unroll
        for (int kp = 0; kp < 8; kp++) {
            uint32_t a0, a1, a2, a3;
            LDSM4(a0, a1, a2, a3, h1b + kp * 32);
            int s = 3 + kp;
#pragma unroll
            for (int hh = 0; hh < 2; hh++) {
                uint4 w01 = Wc0[hh], w23 = Wc1[hh];
                if (s + 1 < NSTREAM) {
                    Wc0[hh] = __ldg(wg1p[hh] + (s + 1) * 64);
                    Wc1[hh] = __ldg(wg1p[hh] + (s + 1) * 64 + 32);
                }
                mma4(acc1[hh], a0, a1, a2, a3, w01, w23);
            }
        }

#pragma unroll
        for (int hh = 0; hh < 2; hh++)
            cell(acc1[hh], cs1[hh], h1e + nxt * MROWS * HSTR, r0, c0, 2 * w + hh);

        __syncthreads();
        cur = nxt;
    }
    // final h1_511 in h1e phase cur; smem weights now dead.

    // ---- head: hidden = relu(h1 @ w1^T + b1) ----
    {
        int ff = tid & 63;
        int mq = tid >> 6;
        const float2* w1p = reinterpret_cast<const float2*>(w1 + ff * HID);
#pragma unroll
        for (int j = 0; j < 4; j++) {
            int m = mq + j * 4;
            float s = b1[ff];
            const uint32_t* hp = h1e + cur * MROWS * HSTR + m * HSTR;
#pragma unroll 8
            for (int p = 0; p < 64; p++) {
                float2 hv = unp_bf2(hp[p]);
                float2 wv = w1p[p];
                s = fmaf(hv.x, wv.x, s);
                s = fmaf(hv.y, wv.y, s);
            }
            hid_s[m * 64 + ff] = fmaxf(s, 0.f);
        }
    }
    __syncthreads();

    // ---- head: out = hidden @ w2^T + b2 ----
    if (tid < 32) {
        int m = tid >> 1, o = tid & 1;
        float s = b2[o];
#pragma unroll 8
        for (int k = 0; k < 64; k++)
            s = fmaf(hid_s[m * 64 + k], w2[o * 64 + k], s);
        out[(B0 + m) * 2 + o] = s;
    }
}

extern "C" void kernel_launch(void* const* d_in, const int* in_sizes, int n_in,
                              void* d_out, int out_size)
{
    const float* hr   = (const float*)d_in[0];
    const float* glu  = (const float*)d_in[1];
    const float* wih0 = (const float*)d_in[2];
    const float* whh0 = (const float*)d_in[3];
    const float* bih0 = (const float*)d_in[4];
    const float* bhh0 = (const float*)d_in[5];
    const float* wih1 = (const float*)d_in[6];
    const float* whh1 = (const float*)d_in[7];
    const float* bih1 = (const float*)d_in[8];
    const float* bhh1 = (const float*)d_in[9];
    const float* w1   = (const float*)d_in[10];
    const float* b1   = (const float*)d_in[11];
    const float* w2   = (const float*)d_in[12];
    const float* b2   = (const float*)d_in[13];
    float* out = (float*)d_out;

    cudaFuncSetAttribute(lstm_main, cudaFuncAttributeMaxDynamicSharedMemorySize, SMEM_SZ);

    prep_kernel<<<128, 256>>>(whh0, wih0, bih0, bhh0, wih1, whh1, bih1, bhh1);
    lstm_main<<<NCTA, NTHR, SMEM_SZ>>>(hr, glu, w1, b1, w2, b2, out);
}